// round 1
// baseline (speedup 1.0000x reference)
#include <cuda_runtime.h>
#include <cstdint>

typedef unsigned long long u64;

#define TILE_B 32
#define THREADS 256
#define LOG_SQRT_2PI 0.9189385332046727f

__device__ __forceinline__ u64 bcast2(float x) {
    u64 r;
    asm("mov.b64 %0, {%1,%2};" : "=l"(r) : "f"(x), "f"(x));
    return r;
}
__device__ __forceinline__ void ffma2(u64& d, u64 a, u64 b) {
    asm("fma.rn.f32x2 %0, %1, %2, %0;" : "+l"(d) : "l"(a), "l"(b));
}
__device__ __forceinline__ float2 unpack2(u64 v) {
    float2 f;
    asm("mov.b64 {%0,%1}, %2;" : "=f"(f.x), "=f"(f.y) : "l"(v));
    return f;
}
__device__ __forceinline__ float lrelu(float v) { return v > 0.f ? v : 0.01f * v; }

// C[32][N] = act(A[32][K] @ W[K][N] + bias), A in smem (row stride K),
// W row-major in global/L2, C written to smem with row stride dstStride.
// Thread layout: CPT=4 cols/thread, COLT=N/4 col-threads, RG row groups.
template <int K, int N, bool RELU>
__device__ __forceinline__ void gemm_tile(
    const float* __restrict__ W, const float* __restrict__ bias,
    const float* __restrict__ sA, float* __restrict__ sC, int dstStride)
{
    constexpr int COLT = N / 4;
    constexpr int RG = THREADS / COLT;
    constexpr int RPT = TILE_B / RG;
    const int t = threadIdx.x;
    const int tx = t % COLT;
    const int ty = t / COLT;
    const int col0 = tx * 4;
    const int row0 = ty * RPT;

    u64 acc[RPT][2];
#pragma unroll
    for (int r = 0; r < RPT; r++) { acc[r][0] = 0ull; acc[r][1] = 0ull; }

    const float* Wt = W + col0;
    ulonglong2 wc[4], wn[4];
#pragma unroll
    for (int kk = 0; kk < 4; kk++)
        wc[kk] = *reinterpret_cast<const ulonglong2*>(Wt + kk * N);

#pragma unroll 2
    for (int k = 0; k < K; k += 4) {
        if (k + 4 < K) {
#pragma unroll
            for (int kk = 0; kk < 4; kk++)
                wn[kk] = *reinterpret_cast<const ulonglong2*>(Wt + (k + 4 + kk) * N);
        }
#pragma unroll
        for (int r = 0; r < RPT; r++) {
            const float4 a4 = *reinterpret_cast<const float4*>(sA + (row0 + r) * K + k);
            u64 a;
            a = bcast2(a4.x); ffma2(acc[r][0], a, wc[0].x); ffma2(acc[r][1], a, wc[0].y);
            a = bcast2(a4.y); ffma2(acc[r][0], a, wc[1].x); ffma2(acc[r][1], a, wc[1].y);
            a = bcast2(a4.z); ffma2(acc[r][0], a, wc[2].x); ffma2(acc[r][1], a, wc[2].y);
            a = bcast2(a4.w); ffma2(acc[r][0], a, wc[3].x); ffma2(acc[r][1], a, wc[3].y);
        }
#pragma unroll
        for (int kk = 0; kk < 4; kk++) wc[kk] = wn[kk];
    }

    const float b0 = bias[col0 + 0];
    const float b1 = bias[col0 + 1];
    const float b2 = bias[col0 + 2];
    const float b3 = bias[col0 + 3];
#pragma unroll
    for (int r = 0; r < RPT; r++) {
        float2 v0 = unpack2(acc[r][0]);
        float2 v1 = unpack2(acc[r][1]);
        float c0 = v0.x + b0, c1 = v0.y + b1, c2 = v1.x + b2, c3 = v1.y + b3;
        if (RELU) { c0 = lrelu(c0); c1 = lrelu(c1); c2 = lrelu(c2); c3 = lrelu(c3); }
        float4 vv = make_float4(c0, c1, c2, c3);
        *reinterpret_cast<float4*>(sC + (row0 + r) * dstStride + col0) = vv;
    }
}

// Shared memory layout (floats)
#define OFF_IN    0        // 32*256 = 8192
#define OFF_GOAL  8192     // 32*128 = 4096
#define OFF_A     12288    // 32*512 = 16384
#define OFF_B     28672    // 32*256 = 8192
#define OFF_C     36864    // 32*256 = 8192 (h / sg, unioned in time)
#define OFF_WGT   45056    // 8*260 = 2080 (Wgate transposed, padded)
#define OFF_GATE  47136    // 32*8 = 256
#define OFF_SUM1  47392    // 640
#define OFF_SUM2  48032    // 640
#define OFF_ACT   48672    // 640
#define SMEM_FLOATS 49312
#define SMEM_BYTES (SMEM_FLOATS * 4)
// p-loop reuse of bufA region:
#define OFF_WP2   OFF_A              // 40*260 = 10400 (Wp2[p] transposed, padded)
#define OFF_PS    (OFF_A + 10400)    // 32*40 = 1280
#define OFF_BP2   (OFF_A + 11680)    // 40

__global__ __launch_bounds__(THREADS, 1) void actor_kernel(
    const float* __restrict__ obs, const float* __restrict__ actions,
    const float* __restrict__ W1, const float* __restrict__ b1,
    const float* __restrict__ W2, const float* __restrict__ b2,
    const float* __restrict__ Wp1, const float* __restrict__ bp1,
    const float* __restrict__ Wp2, const float* __restrict__ bp2,
    const float* __restrict__ Ws1, const float* __restrict__ bs1,
    const float* __restrict__ Ws2, const float* __restrict__ bs2,
    const float* __restrict__ Ws3, const float* __restrict__ bs3,
    const float* __restrict__ Wg1, const float* __restrict__ bg1,
    const float* __restrict__ Wg2, const float* __restrict__ bg2,
    const float* __restrict__ Wg3, const float* __restrict__ bg3,
    const float* __restrict__ Wgate, const float* __restrict__ bgate,
    float* __restrict__ out)
{
    extern __shared__ float sm[];
    float* sIn   = sm + OFF_IN;
    float* sGoal = sm + OFF_GOAL;
    float* sA    = sm + OFF_A;
    float* sB    = sm + OFF_B;
    float* sC    = sm + OFF_C;
    float* sWgT  = sm + OFF_WGT;
    float* sGate = sm + OFF_GATE;
    float* sSum1 = sm + OFF_SUM1;
    float* sSum2 = sm + OFF_SUM2;
    float* sAct  = sm + OFF_ACT;
    float* sWp2  = sm + OFF_WP2;
    float* sPS   = sm + OFF_PS;
    float* sBp2  = sm + OFF_BP2;

    const int t = threadIdx.x;
    const int rowBase = blockIdx.x * TILE_B;

    // ---- load input tiles ----
    {
        const float4* src = reinterpret_cast<const float4*>(obs + (size_t)rowBase * 384);
        for (int i = t; i < 32 * 96; i += THREADS) {
            int b = i / 96, c = i % 96;
            float4 v = src[b * 96 + c];
            if (c < 64) *reinterpret_cast<float4*>(sIn + b * 256 + c * 4) = v;
            else        *reinterpret_cast<float4*>(sGoal + b * 128 + (c - 64) * 4) = v;
        }
        for (int i = t; i < 640; i += THREADS) sAct[i] = actions[(size_t)rowBase * 20 + i];
        for (int i = t; i < 2048; i += THREADS) {
            int k = i >> 3, p = i & 7;
            sWgT[p * 260 + k] = Wgate[i];
        }
        for (int i = t; i < 640; i += THREADS) { sSum1[i] = 0.f; sSum2[i] = 0.f; }
    }
    __syncthreads();

    // ---- gate path ----
    gemm_tile<256, 512, true >(Ws1, bs1, sIn,   sA,       512); __syncthreads();
    gemm_tile<512, 256, true >(Ws2, bs2, sA,    sB,       256); __syncthreads();
    gemm_tile<256, 128, false>(Ws3, bs3, sB,    sC,       256); __syncthreads();
    gemm_tile<128, 512, true >(Wg1, bg1, sGoal, sA,       512); __syncthreads();
    gemm_tile<512, 256, true >(Wg2, bg2, sA,    sB,       256); __syncthreads();
    gemm_tile<256, 128, false>(Wg3, bg3, sB,    sC + 128, 256); __syncthreads();

    // sg = lrelu(concat(s2,g2)) in place
    for (int i = t; i < 32 * 256; i += THREADS) sC[i] = lrelu(sC[i]);
    __syncthreads();

    // gate[b][p] = exp(sg[b] . Wgate[:,p] + bgate[p]); one thread per (b,p)
    {
        const int b = t >> 3, p = t & 7;
        float accv = 0.f;
        const float* wg = sWgT + p * 260;
        const float* row = sC + b * 256;
#pragma unroll 8
        for (int k = 0; k < 256; k += 4) {
            float4 a4 = *reinterpret_cast<const float4*>(row + k);
            float4 w4 = *reinterpret_cast<const float4*>(wg + k);
            accv += a4.x * w4.x + a4.y * w4.y + a4.z * w4.z + a4.w * w4.w;
        }
        sGate[t] = expf(accv + bgate[p]);
    }
    __syncthreads();

    // ---- primitive trunk ----
    gemm_tile<256, 512, true>(W1, b1, sIn, sA, 512); __syncthreads();
    gemm_tile<512, 256, true>(W2, b2, sA,  sB, 256); __syncthreads();
    // sA region now free -> reused for Wp2 staging + ps

    for (int p = 0; p < 8; p++) {
        // stage Wp2[p] transposed (padded rows of 260 to kill bank conflicts) + bias
        const float* wp2 = Wp2 + p * (256 * 40);
        for (int i = t; i < 256 * 40; i += THREADS) {
            int k = i / 40, o = i % 40;
            sWp2[o * 260 + k] = wp2[i];
        }
        if (t < 40) sBp2[t] = bp2[p * 40 + t];
        // h = lrelu(s1 @ Wp1[p] + bp1[p])
        gemm_tile<256, 256, true>(Wp1 + p * (256 * 256), bp1 + p * 256, sB, sC, 256);
        __syncthreads();

        // ps[b][o] = h[b] @ Wp2[p][:,o] + bp2; thread t -> b=t/8, 5 outputs
        {
            const int b = t >> 3;
            const int og = t & 7;
            float accv[5];
#pragma unroll
            for (int q = 0; q < 5; q++) accv[q] = sBp2[og * 5 + q];
            const float* hrow = sC + b * 256;
            for (int k = 0; k < 256; k += 4) {
                float4 h4 = *reinterpret_cast<const float4*>(hrow + k);
#pragma unroll
                for (int q = 0; q < 5; q++) {
                    float4 w4 = *reinterpret_cast<const float4*>(sWp2 + (og * 5 + q) * 260 + k);
                    accv[q] += h4.x * w4.x + h4.y * w4.y + h4.z * w4.z + h4.w * w4.w;
                }
            }
#pragma unroll
            for (int q = 0; q < 5; q++) sPS[b * 40 + og * 5 + q] = accv[q];
        }
        __syncthreads();

        // accumulate mixture sums
        for (int i = t; i < 640; i += THREADS) {
            int b = i / 20, a = i % 20;
            float mu  = sPS[b * 40 + a];
            float sig = expf(sPS[b * 40 + 20 + a]);
            float inv = sGate[b * 8 + p] / sig;
            sSum1[i] += mu * inv;
            sSum2[i] += inv;
        }
        __syncthreads();
    }

    // ---- final log_prob / entropy ----
    if (t < 32) {
        const int b = t;
        float lp = 0.f, ent = 0.f;
#pragma unroll
        for (int a = 0; a < 20; a++) {
            float s1v = sSum1[b * 20 + a];
            float s2v = sSum2[b * 20 + a];
            float mu = s1v / s2v;
            float z = (sAct[b * 20 + a] - mu) * s2v;   // (act-mu)/sigma, sigma=1/s2v
            float ls = -logf(s2v);                     // log(sigma_net)
            lp  += -0.5f * z * z - ls - LOG_SQRT_2PI;
            ent += 0.5f + LOG_SQRT_2PI + ls;
        }
        size_t row = (size_t)rowBase + b;
        out[row * 2 + 0] = lp;
        out[row * 2 + 1] = ent;
    }
}

extern "C" void kernel_launch(void* const* d_in, const int* in_sizes, int n_in,
                              void* d_out, int out_size)
{
    const float* obs    = (const float*)d_in[0];
    const float* actions= (const float*)d_in[1];
    const float* W1     = (const float*)d_in[2];
    const float* b1     = (const float*)d_in[3];
    const float* W2     = (const float*)d_in[4];
    const float* b2     = (const float*)d_in[5];
    const float* Wp1    = (const float*)d_in[6];
    const float* bp1    = (const float*)d_in[7];
    const float* Wp2    = (const float*)d_in[8];
    const float* bp2    = (const float*)d_in[9];
    const float* Ws1    = (const float*)d_in[10];
    const float* bs1    = (const float*)d_in[11];
    const float* Ws2    = (const float*)d_in[12];
    const float* bs2    = (const float*)d_in[13];
    const float* Ws3    = (const float*)d_in[14];
    const float* bs3    = (const float*)d_in[15];
    const float* Wg1    = (const float*)d_in[16];
    const float* bg1    = (const float*)d_in[17];
    const float* Wg2    = (const float*)d_in[18];
    const float* bg2    = (const float*)d_in[19];
    const float* Wg3    = (const float*)d_in[20];
    const float* bg3    = (const float*)d_in[21];
    const float* Wgate  = (const float*)d_in[22];
    const float* bgate  = (const float*)d_in[23];
    float* out = (float*)d_out;

    cudaFuncSetAttribute(actor_kernel,
                         cudaFuncAttributeMaxDynamicSharedMemorySize, SMEM_BYTES);

    const int grid = 65536 / TILE_B;  // 2048 CTAs
    actor_kernel<<<grid, THREADS, SMEM_BYTES>>>(
        obs, actions, W1, b1, W2, b2, Wp1, bp1, Wp2, bp2,
        Ws1, bs1, Ws2, bs2, Ws3, bs3, Wg1, bg1, Wg2, bg2,
        Wg3, bg3, Wgate, bgate, out);
}

// round 2
// speedup vs baseline: 1.0051x; 1.0051x over previous
#include <cuda_runtime.h>
#include <cstdint>

typedef unsigned long long u64;

#define TILE_B 32
#define THREADS 512
#define LOG_SQRT_2PI 0.9189385332046727f

__device__ __forceinline__ u64 bcast2(float x) {
    u64 r;
    asm("mov.b64 %0, {%1,%2};" : "=l"(r) : "f"(x), "f"(x));
    return r;
}
__device__ __forceinline__ void ffma2(u64& d, u64 a, u64 b) {
    asm("fma.rn.f32x2 %0, %1, %2, %0;" : "+l"(d) : "l"(a), "l"(b));
}
__device__ __forceinline__ float2 unpack2(u64 v) {
    float2 f;
    asm("mov.b64 {%0,%1}, %2;" : "=f"(f.x), "=f"(f.y) : "l"(v));
    return f;
}
__device__ __forceinline__ float lrelu(float v) { return v > 0.f ? v : 0.01f * v; }

// C[32][N] = act(A[32][K] @ W[K][N] + bias), A in smem (row stride K),
// W row-major in global/L2, C written to smem with row stride dstStride.
template <int K, int N, bool RELU>
__device__ __forceinline__ void gemm_tile(
    const float* __restrict__ W, const float* __restrict__ bias,
    const float* __restrict__ sA, float* __restrict__ sC, int dstStride)
{
    constexpr int COLT = N / 4;
    constexpr int RG = THREADS / COLT;
    constexpr int RPT = TILE_B / RG;
    const int t = threadIdx.x;
    const int tx = t % COLT;
    const int ty = t / COLT;
    const int col0 = tx * 4;
    const int row0 = ty * RPT;

    u64 acc[RPT][2];
#pragma unroll
    for (int r = 0; r < RPT; r++) { acc[r][0] = 0ull; acc[r][1] = 0ull; }

    const float* Wt = W + col0;
    ulonglong2 wc[4], wn[4];
#pragma unroll
    for (int kk = 0; kk < 4; kk++)
        wc[kk] = *reinterpret_cast<const ulonglong2*>(Wt + kk * N);

#pragma unroll 2
    for (int k = 0; k < K; k += 4) {
        if (k + 4 < K) {
#pragma unroll
            for (int kk = 0; kk < 4; kk++)
                wn[kk] = *reinterpret_cast<const ulonglong2*>(Wt + (k + 4 + kk) * N);
        }
#pragma unroll
        for (int r = 0; r < RPT; r++) {
            const float4 a4 = *reinterpret_cast<const float4*>(sA + (row0 + r) * K + k);
            u64 a;
            a = bcast2(a4.x); ffma2(acc[r][0], a, wc[0].x); ffma2(acc[r][1], a, wc[0].y);
            a = bcast2(a4.y); ffma2(acc[r][0], a, wc[1].x); ffma2(acc[r][1], a, wc[1].y);
            a = bcast2(a4.z); ffma2(acc[r][0], a, wc[2].x); ffma2(acc[r][1], a, wc[2].y);
            a = bcast2(a4.w); ffma2(acc[r][0], a, wc[3].x); ffma2(acc[r][1], a, wc[3].y);
        }
#pragma unroll
        for (int kk = 0; kk < 4; kk++) wc[kk] = wn[kk];
    }

    const float b0 = bias[col0 + 0];
    const float b1 = bias[col0 + 1];
    const float b2 = bias[col0 + 2];
    const float b3 = bias[col0 + 3];
#pragma unroll
    for (int r = 0; r < RPT; r++) {
        float2 v0 = unpack2(acc[r][0]);
        float2 v1 = unpack2(acc[r][1]);
        float c0 = v0.x + b0, c1 = v0.y + b1, c2 = v1.x + b2, c3 = v1.y + b3;
        if (RELU) { c0 = lrelu(c0); c1 = lrelu(c1); c2 = lrelu(c2); c3 = lrelu(c3); }
        float4 vv = make_float4(c0, c1, c2, c3);
        *reinterpret_cast<float4*>(sC + (row0 + r) * dstStride + col0) = vv;
    }
}

// Shared memory layout (floats)
#define OFF_IN    0        // 32*256 = 8192
#define OFF_GOAL  8192     // 32*128 = 4096
#define OFF_A     12288    // 32*512 = 16384
#define OFF_B     28672    // 32*256 = 8192
#define OFF_C     36864    // 32*256 = 8192 (h / sg, unioned in time)
#define OFF_WGT   45056    // 8*260 = 2080 (Wgate transposed, padded)
#define OFF_GATE  47136    // 32*8 = 256
#define OFF_SUM1  47392    // 640
#define OFF_SUM2  48032    // 640
#define OFF_ACT   48672    // 640
#define SMEM_FLOATS 49312
#define SMEM_BYTES (SMEM_FLOATS * 4)
// p-loop reuse of bufA region:
#define OFF_WP2   OFF_A              // 40*260 = 10400 (Wp2[p] transposed, padded)
#define OFF_PS    (OFF_A + 10400)    // 32*40 = 1280
#define OFF_BP2   (OFF_A + 11680)    // 40

__global__ __launch_bounds__(THREADS, 1) void actor_kernel(
    const float* __restrict__ obs, const float* __restrict__ actions,
    const float* __restrict__ W1, const float* __restrict__ b1,
    const float* __restrict__ W2, const float* __restrict__ b2,
    const float* __restrict__ Wp1, const float* __restrict__ bp1,
    const float* __restrict__ Wp2, const float* __restrict__ bp2,
    const float* __restrict__ Ws1, const float* __restrict__ bs1,
    const float* __restrict__ Ws2, const float* __restrict__ bs2,
    const float* __restrict__ Ws3, const float* __restrict__ bs3,
    const float* __restrict__ Wg1, const float* __restrict__ bg1,
    const float* __restrict__ Wg2, const float* __restrict__ bg2,
    const float* __restrict__ Wg3, const float* __restrict__ bg3,
    const float* __restrict__ Wgate, const float* __restrict__ bgate,
    float* __restrict__ out)
{
    extern __shared__ float sm[];
    float* sIn   = sm + OFF_IN;
    float* sGoal = sm + OFF_GOAL;
    float* sA    = sm + OFF_A;
    float* sB    = sm + OFF_B;
    float* sC    = sm + OFF_C;
    float* sWgT  = sm + OFF_WGT;
    float* sGate = sm + OFF_GATE;
    float* sSum1 = sm + OFF_SUM1;
    float* sSum2 = sm + OFF_SUM2;
    float* sAct  = sm + OFF_ACT;
    float* sWp2  = sm + OFF_WP2;
    float* sPS   = sm + OFF_PS;
    float* sBp2  = sm + OFF_BP2;

    const int t = threadIdx.x;
    const int rowBase = blockIdx.x * TILE_B;

    // ---- load input tiles ----
    {
        const float4* src = reinterpret_cast<const float4*>(obs + (size_t)rowBase * 384);
        for (int i = t; i < 32 * 96; i += THREADS) {
            int b = i / 96, c = i % 96;
            float4 v = src[b * 96 + c];
            if (c < 64) *reinterpret_cast<float4*>(sIn + b * 256 + c * 4) = v;
            else        *reinterpret_cast<float4*>(sGoal + b * 128 + (c - 64) * 4) = v;
        }
        for (int i = t; i < 640; i += THREADS) sAct[i] = actions[(size_t)rowBase * 20 + i];
        for (int i = t; i < 2048; i += THREADS) {
            int k = i >> 3, p = i & 7;
            sWgT[p * 260 + k] = Wgate[i];
        }
        for (int i = t; i < 640; i += THREADS) { sSum1[i] = 0.f; sSum2[i] = 0.f; }
    }
    __syncthreads();

    // ---- gate path ----
    gemm_tile<256, 512, true >(Ws1, bs1, sIn,   sA,       512); __syncthreads();
    gemm_tile<512, 256, true >(Ws2, bs2, sA,    sB,       256); __syncthreads();
    gemm_tile<256, 128, false>(Ws3, bs3, sB,    sC,       256); __syncthreads();
    gemm_tile<128, 512, true >(Wg1, bg1, sGoal, sA,       512); __syncthreads();
    gemm_tile<512, 256, true >(Wg2, bg2, sA,    sB,       256); __syncthreads();
    gemm_tile<256, 128, false>(Wg3, bg3, sB,    sC + 128, 256); __syncthreads();

    // sg = lrelu(concat(s2,g2)) in place
    for (int i = t; i < 32 * 256; i += THREADS) sC[i] = lrelu(sC[i]);
    __syncthreads();

    // gate[b][p] = exp(sg[b] . Wgate[:,p] + bgate[p]); one thread per (b,p)
    if (t < 256) {
        const int b = t >> 3, p = t & 7;
        float accv = 0.f;
        const float* wg = sWgT + p * 260;
        const float* row = sC + b * 256;
#pragma unroll 8
        for (int k = 0; k < 256; k += 4) {
            float4 a4 = *reinterpret_cast<const float4*>(row + k);
            float4 w4 = *reinterpret_cast<const float4*>(wg + k);
            accv += a4.x * w4.x + a4.y * w4.y + a4.z * w4.z + a4.w * w4.w;
        }
        sGate[t] = expf(accv + bgate[p]);
    }
    __syncthreads();

    // ---- primitive trunk ----
    gemm_tile<256, 512, true>(W1, b1, sIn, sA, 512); __syncthreads();
    gemm_tile<512, 256, true>(W2, b2, sA,  sB, 256); __syncthreads();
    // sA region now free -> reused for Wp2 staging + ps

    for (int p = 0; p < 8; p++) {
        // stage Wp2[p] transposed (padded rows of 260 to kill bank conflicts) + bias
        const float* wp2 = Wp2 + p * (256 * 40);
        for (int i = t; i < 256 * 40; i += THREADS) {
            int k = i / 40, o = i % 40;
            sWp2[o * 260 + k] = wp2[i];
        }
        if (t < 40) sBp2[t] = bp2[p * 40 + t];
        // h = lrelu(s1 @ Wp1[p] + bp1[p])
        gemm_tile<256, 256, true>(Wp1 + p * (256 * 256), bp1 + p * 256, sB, sC, 256);
        __syncthreads();

        // ps[b][o] = h[b] @ Wp2[p][:,o] + bp2; thread t -> b=t/8, 5 outputs
        if (t < 256) {
            const int b = t >> 3;
            const int og = t & 7;
            float accv[5];
#pragma unroll
            for (int q = 0; q < 5; q++) accv[q] = sBp2[og * 5 + q];
            const float* hrow = sC + b * 256;
            for (int k = 0; k < 256; k += 4) {
                float4 h4 = *reinterpret_cast<const float4*>(hrow + k);
#pragma unroll
                for (int q = 0; q < 5; q++) {
                    float4 w4 = *reinterpret_cast<const float4*>(sWp2 + (og * 5 + q) * 260 + k);
                    accv[q] += h4.x * w4.x + h4.y * w4.y + h4.z * w4.z + h4.w * w4.w;
                }
            }
#pragma unroll
            for (int q = 0; q < 5; q++) sPS[b * 40 + og * 5 + q] = accv[q];
        }
        __syncthreads();

        // accumulate mixture sums
        for (int i = t; i < 640; i += THREADS) {
            int b = i / 20, a = i % 20;
            float mu  = sPS[b * 40 + a];
            float sig = expf(sPS[b * 40 + 20 + a]);
            float inv = sGate[b * 8 + p] / sig;
            sSum1[i] += mu * inv;
            sSum2[i] += inv;
        }
        __syncthreads();
    }

    // ---- final log_prob / entropy ----
    if (t < 32) {
        const int b = t;
        float lp = 0.f, ent = 0.f;
#pragma unroll
        for (int a = 0; a < 20; a++) {
            float s1v = sSum1[b * 20 + a];
            float s2v = sSum2[b * 20 + a];
            float mu = s1v / s2v;
            float z = (sAct[b * 20 + a] - mu) * s2v;   // (act-mu)/sigma, sigma=1/s2v
            float ls = -logf(s2v);                     // log(sigma_net)
            lp  += -0.5f * z * z - ls - LOG_SQRT_2PI;
            ent += 0.5f + LOG_SQRT_2PI + ls;
        }
        size_t row = (size_t)rowBase + b;
        out[row * 2 + 0] = lp;
        out[row * 2 + 1] = ent;
    }
}

extern "C" void kernel_launch(void* const* d_in, const int* in_sizes, int n_in,
                              void* d_out, int out_size)
{
    const float* obs    = (const float*)d_in[0];
    const float* actions= (const float*)d_in[1];
    const float* W1     = (const float*)d_in[2];
    const float* b1     = (const float*)d_in[3];
    const float* W2     = (const float*)d_in[4];
    const float* b2     = (const float*)d_in[5];
    const float* Wp1    = (const float*)d_in[6];
    const float* bp1    = (const float*)d_in[7];
    const float* Wp2    = (const float*)d_in[8];
    const float* bp2    = (const float*)d_in[9];
    const float* Ws1    = (const float*)d_in[10];
    const float* bs1    = (const float*)d_in[11];
    const float* Ws2    = (const float*)d_in[12];
    const float* bs2    = (const float*)d_in[13];
    const float* Ws3    = (const float*)d_in[14];
    const float* bs3    = (const float*)d_in[15];
    const float* Wg1    = (const float*)d_in[16];
    const float* bg1    = (const float*)d_in[17];
    const float* Wg2    = (const float*)d_in[18];
    const float* bg2    = (const float*)d_in[19];
    const float* Wg3    = (const float*)d_in[20];
    const float* bg3    = (const float*)d_in[21];
    const float* Wgate  = (const float*)d_in[22];
    const float* bgate  = (const float*)d_in[23];
    float* out = (float*)d_out;

    cudaFuncSetAttribute(actor_kernel,
                         cudaFuncAttributeMaxDynamicSharedMemorySize, SMEM_BYTES);

    const int grid = 65536 / TILE_B;  // 2048 CTAs
    actor_kernel<<<grid, THREADS, SMEM_BYTES>>>(
        obs, actions, W1, b1, W2, b2, Wp1, bp1, Wp2, bp2,
        Ws1, bs1, Ws2, bs2, Ws3, bs3, Wg1, bg1, Wg2, bg2,
        Wg3, bg3, Wgate, bgate, out);
}